// round 6
// baseline (speedup 1.0000x reference)
#include <cuda_runtime.h>
#include <cuda_bf16.h>
#include <stdint.h>

#define NN 8192
#define DD 128
#define WORDS_PER_ROW 256          // 8192 bits / 32
#define MAXNNZ 128                 // per-row capacity (mean ~32; Poisson tail safe)

// -------- scratch (no allocations allowed) --------
__device__ __align__(16) uint32_t g_mask[NN * WORDS_PER_ROW];   // 8 MB adjacency bitmask (edges only, no eye)
__device__ __align__(16) int      g_deg[NN];                    // dedup'd edge degree (no eye)
__device__ __align__(16) float    g_ys[NN * DD];                // ys[j] = d_j^{-1/2} * (x @ W^T)[j]
__device__ int g_is64;                                          // edge_index dtype flag (auto-detected)

// K1: zero mask + deg; block 0 also detects int64 vs int32 edge_index
// (values < 8192 -> for int64 every odd 32-bit word is 0; P(false positive for int32) ~ 8192^-128).
__global__ void k_zero(const uint32_t* __restrict__ raw) {
    if (blockIdx.x == 0) {
        int t = threadIdx.x;
        int nz = (t < 128) ? (raw[2 * t + 1] != 0u) : 0;
        int any = __syncthreads_or(nz);
        if (t == 0) g_is64 = !any;
    }
    const uint4 z = make_uint4(0u, 0u, 0u, 0u);
    int tid = blockIdx.x * blockDim.x + threadIdx.x;
    int stride = gridDim.x * blockDim.x;
    uint4* pm = reinterpret_cast<uint4*>(g_mask);
    for (int i = tid; i < NN * WORDS_PER_ROW / 4; i += stride) pm[i] = z;
    uint4* pd = reinterpret_cast<uint4*>(g_deg);
    for (int i = tid; i < NN / 4; i += stride) pd[i] = z;
}

// K2: scatter edges into bitmask; atomicOr's OLD value identifies the unique setter of each
// bit -> exact dedup'd degree via atomicAdd (per-row-distinct addresses, cheap L2 atomics).
__global__ void k_scatter(const void* __restrict__ eiraw, int E) {
    int e = blockIdx.x * blockDim.x + threadIdx.x;
    if (e >= E) return;
    int r, c;
    if (g_is64) {
        const long long* ei = (const long long*)eiraw;
        r = (int)ei[e];
        c = (int)ei[E + e];
    } else {
        const int* ei = (const int*)eiraw;
        r = ei[e];
        c = ei[E + e];
    }
    r &= (NN - 1);
    c &= (NN - 1);
    uint32_t bit = 1u << (c & 31);
    uint32_t old = atomicOr(&g_mask[r * WORDS_PER_ROW + (c >> 5)], bit);
    if (!(old & bit)) atomicAdd(&g_deg[r], 1);
}

// K3: ys = diag(d^{-1/2}) * (x @ W^T).  M=8192, N=128, K=128 fp32, f32x2 packed FFMA.
// Block: 128 threads (32x4); thread tile: 2 feature-pairs x 8 rows (16 fma.rn.f32x2 per k).
__global__ void k_gemm_xw(const float* __restrict__ x, const float* __restrict__ W) {
    __shared__ float sW[64 * 130];   // sW[k*130 + f]; even pitch keeps float2 loads 8B-aligned
    __shared__ float sx[32 * 64];    // sx[r*64 + k]  : broadcast reads
    int t  = threadIdx.x;
    int tx = t & 31;                 // feature-pair lane: features {2tx,2tx+1} and {64+2tx,65+2tx}
    int ty = t >> 5;                 // row group
    int r0 = blockIdx.x * 32;

    unsigned long long acc[2][8];
    #pragma unroll
    for (int q = 0; q < 2; q++)
        #pragma unroll
        for (int p = 0; p < 8; p++) acc[q][p] = 0ull;

    for (int ch = 0; ch < 2; ch++) {
        __syncthreads();
        for (int i = t; i < 128 * 64; i += 128) {       // sW[k][f] = W[f][ch*64+k]
            int f = i >> 6, k = i & 63;
            sW[k * 130 + f] = W[f * 128 + ch * 64 + k];
        }
        for (int i = t; i < 32 * 64; i += 128) {        // sx[r][k] = x[r0+r][ch*64+k]
            int r = i >> 6, k = i & 63;
            sx[r * 64 + k] = x[(r0 + r) * 128 + ch * 64 + k];
        }
        __syncthreads();
        #pragma unroll 4
        for (int k = 0; k < 64; k++) {
            float2 w0 = *reinterpret_cast<const float2*>(&sW[k * 130 + 2 * tx]);
            float2 w1 = *reinterpret_cast<const float2*>(&sW[k * 130 + 64 + 2 * tx]);
            unsigned long long wv0, wv1;
            asm("mov.b64 %0, {%1, %2};" : "=l"(wv0) : "f"(w0.x), "f"(w0.y));
            asm("mov.b64 %0, {%1, %2};" : "=l"(wv1) : "f"(w1.x), "f"(w1.y));
            #pragma unroll
            for (int p = 0; p < 8; p++) {
                float xv = sx[(ty + 4 * p) * 64 + k];
                unsigned long long xx;
                asm("mov.b64 %0, {%1, %1};" : "=l"(xx) : "f"(xv));
                asm("fma.rn.f32x2 %0, %1, %2, %0;" : "+l"(acc[0][p]) : "l"(xx), "l"(wv0));
                asm("fma.rn.f32x2 %0, %1, %2, %0;" : "+l"(acc[1][p]) : "l"(xx), "l"(wv1));
            }
        }
    }
    #pragma unroll
    for (int p = 0; p < 8; p++) {
        int r = r0 + ty + 4 * p;
        float d = rsqrtf((float)g_deg[r] + 1.0f);   // +eye in degree
        #pragma unroll
        for (int q = 0; q < 2; q++) {
            float lo, hi;
            asm("mov.b64 {%0, %1}, %2;" : "=f"(lo), "=f"(hi) : "l"(acc[q][p]));
            float2 v = make_float2(d * lo, d * hi);
            *reinterpret_cast<float2*>(&g_ys[r * 128 + 64 * q + 2 * tx]) = v;
        }
    }
}

// K4: fused extract + aggregate.  Block(128) per row i, thread t = feature.
// Threads scan 2 mask words each into a shared neighbor list (order irrelevant: it's a sum),
// then gather-sum ys rows. out[i] = d_i^{-1/2} * (sum_j ys[j] + ys[i]) + b.
__global__ void k_aggregate(const float* __restrict__ bias, float* __restrict__ out) {
    int i = blockIdx.x;
    int t = threadIdx.x;
    __shared__ int sj[MAXNNZ];
    __shared__ int s_cnt;
    if (t == 0) s_cnt = 0;
    __syncthreads();

    // inline bit extraction: thread t handles words 2t, 2t+1 (coalesced uint2)
    const uint2 w2 = reinterpret_cast<const uint2*>(g_mask + i * WORDS_PER_ROW)[t];
    uint32_t w;
    w = w2.x;
    while (w) {
        int b = __ffs(w) - 1; w &= w - 1;
        int p = atomicAdd(&s_cnt, 1);
        if (p < MAXNNZ) sj[p] = t * 64 + b;
    }
    w = w2.y;
    while (w) {
        int b = __ffs(w) - 1; w &= w - 1;
        int p = atomicAdd(&s_cnt, 1);
        if (p < MAXNNZ) sj[p] = t * 64 + 32 + b;
    }
    __syncthreads();
    int nn = s_cnt < MAXNNZ ? s_cnt : MAXNNZ;

    float acc = g_ys[i * 128 + t];     // +eye diagonal term (self-edge bit in list -> diag 2 correct)
    int n = 0;
    for (; n + 4 <= nn; n += 4) {
        int j0 = sj[n], j1 = sj[n + 1], j2 = sj[n + 2], j3 = sj[n + 3];
        float a0 = g_ys[j0 * 128 + t];
        float a1 = g_ys[j1 * 128 + t];
        float a2 = g_ys[j2 * 128 + t];
        float a3 = g_ys[j3 * 128 + t];
        acc += (a0 + a1) + (a2 + a3);
    }
    for (; n < nn; n++) acc += g_ys[sj[n] * 128 + t];
    float di = rsqrtf((float)g_deg[i] + 1.0f);
    out[i * 128 + t] = di * acc + bias[t];
}

extern "C" void kernel_launch(void* const* d_in, const int* in_sizes, int n_in,
                              void* d_out, int out_size) {
    const float* x  = (const float*)d_in[0];
    const void*  ei = d_in[1];
    const float* W  = (const float*)d_in[2];
    const float* b  = (const float*)d_in[3];
    float* out = (float*)d_out;
    int E = in_sizes[1] / 2;   // element count / 2, dtype-independent

    k_zero<<<512, 256>>>((const uint32_t*)ei);
    k_scatter<<<(E + 255) / 256, 256>>>(ei, E);
    k_gemm_xw<<<NN / 32, 128>>>(x, W);
    k_aggregate<<<NN, 128>>>(b, out);
}

// round 7
// speedup vs baseline: 1.4562x; 1.4562x over previous
#include <cuda_runtime.h>
#include <cuda_bf16.h>
#include <stdint.h>

#define NN 8192
#define DD 128
#define WORDS_PER_ROW 256          // 8192 bits / 32
#define MAXNNZ 128                 // per-row capacity (mean ~32; Poisson tail safe)

// -------- scratch (no allocations allowed) --------
__device__ __align__(16) uint32_t g_mask[NN * WORDS_PER_ROW];   // 8 MB adjacency bitmask (edges only, no eye)
__device__ __align__(16) int      g_deg[NN];                    // dedup'd edge degree (no eye)
__device__ __align__(16) float    g_ys[NN * DD];                // ys[j] = d_j^{-1/2} * (x @ W^T)[j]
__device__ int g_is64;                                          // edge_index dtype flag (auto-detected)

// K1: zero mask + deg; block 0 also detects int64 vs int32 edge_index
// (values < 8192 -> for int64 every odd 32-bit word is 0; P(false positive) ~ 8192^-128).
__global__ void k_zero(const uint32_t* __restrict__ raw) {
    if (blockIdx.x == 0) {
        int t = threadIdx.x;
        int nz = (t < 128) ? (raw[2 * t + 1] != 0u) : 0;
        int any = __syncthreads_or(nz);
        if (t == 0) g_is64 = !any;
    }
    const uint4 z = make_uint4(0u, 0u, 0u, 0u);
    int tid = blockIdx.x * blockDim.x + threadIdx.x;
    int stride = gridDim.x * blockDim.x;
    uint4* pm = reinterpret_cast<uint4*>(g_mask);
    for (int i = tid; i < NN * WORDS_PER_ROW / 4; i += stride) pm[i] = z;
    uint4* pd = reinterpret_cast<uint4*>(g_deg);
    for (int i = tid; i < NN / 4; i += stride) pd[i] = z;
}

// K2: scatter edges; atomicOr's OLD value identifies the unique setter of each bit
// -> exact dedup'd degree via atomicAdd (addresses spread across 8192 rows).
__global__ void k_scatter(const void* __restrict__ eiraw, int E) {
    int e = blockIdx.x * blockDim.x + threadIdx.x;
    if (e >= E) return;
    int r, c;
    if (g_is64) {
        const long long* ei = (const long long*)eiraw;
        r = (int)ei[e];
        c = (int)ei[E + e];
    } else {
        const int* ei = (const int*)eiraw;
        r = ei[e];
        c = ei[E + e];
    }
    r &= (NN - 1);
    c &= (NN - 1);
    uint32_t bit = 1u << (c & 31);
    uint32_t old = atomicOr(&g_mask[r * WORDS_PER_ROW + (c >> 5)], bit);
    if (!(old & bit)) atomicAdd(&g_deg[r], 1);
}

// K3: ys = diag(d^{-1/2}) * (x @ W^T).  M=8192, N=128, K=128 fp32 (scalar FFMA tile, R4-proven).
__global__ void k_gemm_xw(const float* __restrict__ x, const float* __restrict__ W) {
    __shared__ float sW[64 * 129];   // sW[k*129 + f] : conflict-free
    __shared__ float sx[32 * 64];    // sx[r*64 + k]  : broadcast reads
    int t  = threadIdx.x;
    int tx = t & 31;                 // feature lane
    int ty = t >> 5;                 // row group
    int r0 = blockIdx.x * 32;

    float acc[4][8];
    #pragma unroll
    for (int q = 0; q < 4; q++)
        #pragma unroll
        for (int p = 0; p < 8; p++) acc[q][p] = 0.f;

    for (int ch = 0; ch < 2; ch++) {
        __syncthreads();
        for (int i = t; i < 128 * 64; i += 128) {       // sW[k][f] = W[f][ch*64+k]
            int f = i >> 6, k = i & 63;
            sW[k * 129 + f] = W[f * 128 + ch * 64 + k];
        }
        for (int i = t; i < 32 * 64; i += 128) {        // sx[r][k] = x[r0+r][ch*64+k]
            int r = i >> 6, k = i & 63;
            sx[r * 64 + k] = x[(r0 + r) * 128 + ch * 64 + k];
        }
        __syncthreads();
        #pragma unroll 8
        for (int k = 0; k < 64; k++) {
            float wv[4];
            #pragma unroll
            for (int q = 0; q < 4; q++) wv[q] = sW[k * 129 + tx + 32 * q];
            #pragma unroll
            for (int p = 0; p < 8; p++) {
                float xv = sx[(ty + 4 * p) * 64 + k];
                #pragma unroll
                for (int q = 0; q < 4; q++) acc[q][p] += xv * wv[q];
            }
        }
    }
    #pragma unroll
    for (int p = 0; p < 8; p++) {
        int r = r0 + ty + 4 * p;
        float d = rsqrtf((float)g_deg[r] + 1.0f);       // +eye in degree
        #pragma unroll
        for (int q = 0; q < 4; q++)
            g_ys[r * 128 + tx + 32 * q] = d * acc[q][p];
    }
}

// K4: fused extract + aggregate. Block(128) per row i = 4 warps.
// Extraction: scan-based compaction (no contended shared atomics).
// Gather: float4 per lane (32 lanes = full 128-float row), neighbor list strided across 4 warps,
// warp partials combined via smem. Self row appended to the list (= the +eye term; a self-edge
// bit also in the list makes the diagonal 2, matching the reference).
__global__ void k_aggregate(const float* __restrict__ bias, float* __restrict__ out) {
    int i    = blockIdx.x;
    int t    = threadIdx.x;
    int lane = t & 31;
    int w    = t >> 5;
    __shared__ int   sj[MAXNNZ + 1];
    __shared__ int   s_wsum[4];
    __shared__ float4 s_part[4][32];

    // 1) load mask words (thread t -> words 2t,2t+1, coalesced uint2) and count
    const uint2 w2 = reinterpret_cast<const uint2*>(g_mask + i * WORDS_PER_ROW)[t];
    int cnt = __popc(w2.x) + __popc(w2.y);

    // warp-inclusive scan of cnt
    int pre = cnt;
    #pragma unroll
    for (int o = 1; o < 32; o <<= 1) {
        int v = __shfl_up_sync(0xFFFFFFFFu, pre, o);
        if (lane >= o) pre += v;
    }
    if (lane == 31) s_wsum[w] = pre;           // warp total
    __syncthreads();

    int base = 0;
    #pragma unroll
    for (int q = 0; q < 4; q++) base += (q < w) ? s_wsum[q] : 0;
    int nn = s_wsum[0] + s_wsum[1] + s_wsum[2] + s_wsum[3];
    int pos = base + (pre - cnt);              // exclusive position for this thread

    // 2) emit set-bit indices
    uint32_t word = w2.x;
    while (word) {
        int b = __ffs(word) - 1; word &= word - 1;
        if (pos < MAXNNZ) sj[pos] = t * 64 + b;
        pos++;
    }
    word = w2.y;
    while (word) {
        int b = __ffs(word) - 1; word &= word - 1;
        if (pos < MAXNNZ) sj[pos] = t * 64 + 32 + b;
        pos++;
    }
    if (nn > MAXNNZ) nn = MAXNNZ;
    if (t == 0) sj[nn] = i;                    // +eye: row i itself, once
    int nn1 = nn + 1;
    __syncthreads();

    // 3) gather: warp w takes neighbors w, w+4, w+8, ...; each lane reads float4 (16B)
    float4 acc = make_float4(0.f, 0.f, 0.f, 0.f);
    #pragma unroll 2
    for (int n = w; n < nn1; n += 4) {
        int j = sj[n];
        float4 v = *reinterpret_cast<const float4*>(&g_ys[j * 128 + lane * 4]);
        acc.x += v.x; acc.y += v.y; acc.z += v.z; acc.w += v.w;
    }
    s_part[w][lane] = acc;
    __syncthreads();

    // 4) combine 4 warp partials; thread t owns output feature t
    const float* sp = reinterpret_cast<const float*>(s_part);
    float r = sp[0 * 128 + t] + sp[1 * 128 + t] + sp[2 * 128 + t] + sp[3 * 128 + t];
    float di = rsqrtf((float)g_deg[i] + 1.0f);
    out[i * 128 + t] = di * r + bias[t];
}

extern "C" void kernel_launch(void* const* d_in, const int* in_sizes, int n_in,
                              void* d_out, int out_size) {
    const float* x  = (const float*)d_in[0];
    const void*  ei = d_in[1];
    const float* W  = (const float*)d_in[2];
    const float* b  = (const float*)d_in[3];
    float* out = (float*)d_out;
    int E = in_sizes[1] / 2;   // element count / 2, dtype-independent

    k_zero<<<512, 256>>>((const uint32_t*)ei);
    k_scatter<<<(E + 255) / 256, 256>>>(ei, E);
    k_gemm_xw<<<NN / 32, 128>>>(x, W);
    k_aggregate<<<NN, 128>>>(b, out);
}